// round 8
// baseline (speedup 1.0000x reference)
#include <cuda_runtime.h>
#include <stdint.h>

// GridGCNNearNeighbors, R8: SoA(x,y,z,|p|^2) planes + float4 loads + prefetch
// + persistent warps with atomic work queue (tail-balance).
//
// For each (b, s) centroid, emit the 32 smallest point indices with squared
// distance <= 0.2^2 (reference: mask -> sort ascending indices -> take 32 ==
// first-32 in-radius indices in index order), padding with the first hit.
//
// Inputs identified by element count (harness delivers int64 as int32):
//   pos        float32 [8, 8192, 3]  -> 196608 elements (unique)
//   centroids  int32   [8, 2048]     -> 16384 elements (unique)
// Output: float32 [8, 2048, 32] (indices stored as floats, exact <= 8192)

namespace {
constexpr int Bb = 8;
constexpr int Nn = 8192;
constexpr int Ss = 2048;
constexpr int Kk = 32;
constexpr float THR = 0.04f;  // (float)(0.2**2)
constexpr int TOTAL = Bb * Ss; // 16384 centroids
}

// SoA scratch planes (static device mem; 16B-aligned for float4 loads)
__device__ __align__(16) float g_x[Bb * Nn];
__device__ __align__(16) float g_y[Bb * Nn];
__device__ __align__(16) float g_z[Bb * Nn];
__device__ __align__(16) float g_s[Bb * Nn];  // |p|^2, same expression/bits as inline
__device__ int g_counter;

__global__ __launch_bounds__(256)
void soa_transpose_kernel(const float* __restrict__ pos) {
    const int i = blockIdx.x * blockDim.x + threadIdx.x;
    if (i == 0) g_counter = 0;  // deterministic per-launch reset (runs before scan)
    if (i >= Bb * Nn) return;
    const float* p = pos + (size_t)i * 3;
    const float x = p[0], y = p[1], z = p[2];
    g_x[i] = x;
    g_y[i] = y;
    g_z[i] = z;
    g_s[i] = x * x + y * y + z * z;  // identical expression shape to R7 inline sp
}

__global__ __launch_bounds__(256)
void gridgcn_knn_kernel(const int* __restrict__ centroids,
                        float* __restrict__ out) {
    const int lane = threadIdx.x & 31;
    const unsigned below = (1u << lane) - 1u;
    const unsigned mybit = 1u << lane;

    for (;;) {
        // Warp pulls next centroid from the global queue
        int wid;
        if (lane == 0) wid = atomicAdd(&g_counter, 1);
        wid = __shfl_sync(0xffffffffu, wid, 0);
        if (wid >= TOTAL) return;

        const int b = wid >> 11;              // / 2048
        const int c = centroids[wid] & (Nn - 1);
        const int boff = b * Nn;

        const float* __restrict__ px = g_x + boff;
        const float* __restrict__ py = g_y + boff;
        const float* __restrict__ pz = g_z + boff;

        // Center coordinates (warp-uniform broadcast; same bits as original pos)
        const float cx = px[c];
        const float cy = py[c];
        const float cz = pz[c];
        // Same expansion form as reference: ||c||^2 + ||p||^2 - 2 c.p
        const float sc = cx * cx + cy * cy + cz * cz;

        const float4* __restrict__ px4 = (const float4*)px;
        const float4* __restrict__ py4 = (const float4*)py;
        const float4* __restrict__ pz4 = (const float4*)pz;
        const float4* __restrict__ ps4 = (const float4*)(g_s + boff);

        float* __restrict__ o = out + (size_t)wid * Kk;

        int have = 0;
        int first_idx = Nn;

        // Prefetch tile 0: lane handles points base + 4*lane + {0,1,2,3}
        float4 x4 = px4[lane], y4 = py4[lane], z4 = pz4[lane], s4 = ps4[lane];

        #pragma unroll 1
        for (int base = 0; base < Nn; base += 128) {
            // Prefetch next tile before consuming this one
            float4 nx4, ny4, nz4, ns4;
            const int nbase = base + 128;
            if (nbase < Nn) {
                const int q = (nbase >> 2) + lane;
                nx4 = px4[q]; ny4 = py4[q]; nz4 = pz4[q]; ns4 = ps4[q];
            }

            const float d20 = sc + s4.x - 2.0f * (cx * x4.x + cy * y4.x + cz * z4.x);
            const float d21 = sc + s4.y - 2.0f * (cx * x4.y + cy * y4.y + cz * z4.y);
            const float d22 = sc + s4.z - 2.0f * (cx * x4.z + cy * y4.z + cz * z4.z);
            const float d23 = sc + s4.w - 2.0f * (cx * x4.w + cy * y4.w + cz * z4.w);

            // mask_k bit l  <->  point base + 4*l + k  (lane-major index order)
            const unsigned m0 = __ballot_sync(0xffffffffu, d20 <= THR);
            const unsigned m1 = __ballot_sync(0xffffffffu, d21 <= THR);
            const unsigned m2 = __ballot_sync(0xffffffffu, d22 <= THR);
            const unsigned m3 = __ballot_sync(0xffffffffu, d23 <= THR);

            if (m0 | m1 | m2 | m3) {
                if (have == 0) {
                    int cand = 0x7fffffff;
                    if (m0) cand = min(cand, 4 * (__ffs(m0) - 1) + 0);
                    if (m1) cand = min(cand, 4 * (__ffs(m1) - 1) + 1);
                    if (m2) cand = min(cand, 4 * (__ffs(m2) - 1) + 2);
                    if (m3) cand = min(cand, 4 * (__ffs(m3) - 1) + 3);
                    first_idx = base + cand;
                }
                // Hits at point indices below this lane's k=0 point
                const int pre = __popc(m0 & below) + __popc(m1 & below) +
                                __popc(m2 & below) + __popc(m3 & below);
                const int p0 = base + 4 * lane;
                int s = have + pre;
                if (m0 & mybit) { if (s < Kk) o[s] = (float)(p0 + 0); s++; }
                if (m1 & mybit) { if (s < Kk) o[s] = (float)(p0 + 1); s++; }
                if (m2 & mybit) { if (s < Kk) o[s] = (float)(p0 + 2); s++; }
                if (m3 & mybit) { if (s < Kk) o[s] = (float)(p0 + 3); s++; }

                have += __popc(m0) + __popc(m1) + __popc(m2) + __popc(m3);
                if (have >= Kk) break;
            }
            x4 = nx4; y4 = ny4; z4 = nz4; s4 = ns4;
        }

        // Pad tail with group_first (warp-uniform value)
        const float fpad = (float)first_idx;
        for (int i = have + lane; i < Kk; i += 32) o[i] = fpad;
    }
}

extern "C" void kernel_launch(void* const* d_in, const int* in_sizes, int n_in,
                              void* d_out, int out_size) {
    (void)out_size;
    const float* pos = nullptr;
    const int* centroids = nullptr;
    for (int i = 0; i < n_in; i++) {
        if (in_sizes[i] == Bb * Nn * 3)      pos = (const float*)d_in[i];
        else if (in_sizes[i] == Bb * Ss)     centroids = (const int*)d_in[i];
    }
    float* out = (float*)d_out;

    soa_transpose_kernel<<<(Bb * Nn + 255) / 256, 256>>>(pos);

    // Persistent grid: ~8 blocks/SM x 152 SMs; warps self-schedule via queue
    gridgcn_knn_kernel<<<152 * 8, 256>>>(centroids, out);
}

// round 9
// speedup vs baseline: 1.1655x; 1.1655x over previous
#include <cuda_runtime.h>
#include <stdint.h>

// GridGCNNearNeighbors, R9: R7 structure (static mapping, 64-thr blocks,
// float4 SoA, next-tile prefetch) + precomputed |p|^2 plane (validated in R8).
//
// For each (b, s) centroid, emit the 32 smallest point indices with squared
// distance <= 0.2^2 (reference: mask -> sort ascending indices -> take 32 ==
// first-32 in-radius indices in index order), padding with the first hit.
//
// Inputs identified by element count (harness delivers int64 as int32):
//   pos        float32 [8, 8192, 3]  -> 196608 elements (unique)
//   centroids  int32   [8, 2048]     -> 16384 elements (unique)
// Output: float32 [8, 2048, 32] (indices stored as floats, exact <= 8192)

namespace {
constexpr int Bb = 8;
constexpr int Nn = 8192;
constexpr int Ss = 2048;
constexpr int Kk = 32;
constexpr float THR = 0.04f;  // (float)(0.2**2)
}

// SoA scratch planes (static device mem; 16B-aligned for float4 loads)
__device__ __align__(16) float g_x[Bb * Nn];
__device__ __align__(16) float g_y[Bb * Nn];
__device__ __align__(16) float g_z[Bb * Nn];
__device__ __align__(16) float g_s[Bb * Nn];  // |p|^2 (bits validated in R8)

__global__ __launch_bounds__(256)
void soa_transpose_kernel(const float* __restrict__ pos) {
    const int i = blockIdx.x * blockDim.x + threadIdx.x;
    if (i >= Bb * Nn) return;
    const float* p = pos + (size_t)i * 3;
    const float x = p[0], y = p[1], z = p[2];
    g_x[i] = x;
    g_y[i] = y;
    g_z[i] = z;
    g_s[i] = x * x + y * y + z * z;
}

__global__ __launch_bounds__(64)
void gridgcn_knn_kernel(const int* __restrict__ centroids,
                        float* __restrict__ out) {
    const int warp_id = (blockIdx.x << 1) | (threadIdx.x >> 5);
    const int lane = threadIdx.x & 31;
    if (warp_id >= Bb * Ss) return;

    const int b = warp_id >> 11;          // / 2048
    const int c = centroids[warp_id] & (Nn - 1);
    const int boff = b * Nn;

    const float* __restrict__ px = g_x + boff;
    const float* __restrict__ py = g_y + boff;
    const float* __restrict__ pz = g_z + boff;

    // Center coordinates (warp-uniform broadcast; same bits as original pos)
    const float cx = px[c];
    const float cy = py[c];
    const float cz = pz[c];
    // Same expansion form as reference: ||c||^2 + ||p||^2 - 2 c.p
    const float sc = cx * cx + cy * cy + cz * cz;

    const float4* __restrict__ px4 = (const float4*)px;
    const float4* __restrict__ py4 = (const float4*)py;
    const float4* __restrict__ pz4 = (const float4*)pz;
    const float4* __restrict__ ps4 = (const float4*)(g_s + boff);

    float* __restrict__ o = out + (size_t)warp_id * Kk;

    int have = 0;
    int first_idx = Nn;
    const unsigned below = (1u << lane) - 1u;
    const unsigned mybit = 1u << lane;

    // Prefetch tile 0: lane handles points base + 4*lane + {0,1,2,3}
    float4 x4 = px4[lane], y4 = py4[lane], z4 = pz4[lane], s4 = ps4[lane];

    #pragma unroll 1
    for (int base = 0; base < Nn; base += 128) {
        // Prefetch next tile before consuming this one
        float4 nx4, ny4, nz4, ns4;
        const int nbase = base + 128;
        if (nbase < Nn) {
            const int q = (nbase >> 2) + lane;
            nx4 = px4[q]; ny4 = py4[q]; nz4 = pz4[q]; ns4 = ps4[q];
        }

        const float d20 = sc + s4.x - 2.0f * (cx * x4.x + cy * y4.x + cz * z4.x);
        const float d21 = sc + s4.y - 2.0f * (cx * x4.y + cy * y4.y + cz * z4.y);
        const float d22 = sc + s4.z - 2.0f * (cx * x4.z + cy * y4.z + cz * z4.z);
        const float d23 = sc + s4.w - 2.0f * (cx * x4.w + cy * y4.w + cz * z4.w);

        // mask_k bit l  <->  point base + 4*l + k  (lane-major index order)
        const unsigned m0 = __ballot_sync(0xffffffffu, d20 <= THR);
        const unsigned m1 = __ballot_sync(0xffffffffu, d21 <= THR);
        const unsigned m2 = __ballot_sync(0xffffffffu, d22 <= THR);
        const unsigned m3 = __ballot_sync(0xffffffffu, d23 <= THR);

        if (m0 | m1 | m2 | m3) {
            if (have == 0) {
                int cand = 0x7fffffff;
                if (m0) cand = min(cand, 4 * (__ffs(m0) - 1) + 0);
                if (m1) cand = min(cand, 4 * (__ffs(m1) - 1) + 1);
                if (m2) cand = min(cand, 4 * (__ffs(m2) - 1) + 2);
                if (m3) cand = min(cand, 4 * (__ffs(m3) - 1) + 3);
                first_idx = base + cand;
            }
            // Hits at point indices below this lane's k=0 point
            const int pre = __popc(m0 & below) + __popc(m1 & below) +
                            __popc(m2 & below) + __popc(m3 & below);
            const int p0 = base + 4 * lane;
            int s = have + pre;
            if (m0 & mybit) { if (s < Kk) o[s] = (float)(p0 + 0); s++; }
            if (m1 & mybit) { if (s < Kk) o[s] = (float)(p0 + 1); s++; }
            if (m2 & mybit) { if (s < Kk) o[s] = (float)(p0 + 2); s++; }
            if (m3 & mybit) { if (s < Kk) o[s] = (float)(p0 + 3); s++; }

            have += __popc(m0) + __popc(m1) + __popc(m2) + __popc(m3);
            if (have >= Kk) break;
        }
        x4 = nx4; y4 = ny4; z4 = nz4; s4 = ns4;
    }

    // Pad tail with group_first (warp-uniform value)
    const float fpad = (float)first_idx;
    for (int i = have + lane; i < Kk; i += 32) o[i] = fpad;
}

extern "C" void kernel_launch(void* const* d_in, const int* in_sizes, int n_in,
                              void* d_out, int out_size) {
    (void)out_size;
    const float* pos = nullptr;
    const int* centroids = nullptr;
    for (int i = 0; i < n_in; i++) {
        if (in_sizes[i] == Bb * Nn * 3)      pos = (const float*)d_in[i];
        else if (in_sizes[i] == Bb * Ss)     centroids = (const int*)d_in[i];
    }
    float* out = (float*)d_out;

    soa_transpose_kernel<<<(Bb * Nn + 255) / 256, 256>>>(pos);

    const int total_warps = Bb * Ss;           // 16384
    const int threads = 64;                    // 2 warps/block
    const int blocks = total_warps / 2;        // 8192
    gridgcn_knn_kernel<<<blocks, threads>>>(centroids, out);
}

// round 10
// speedup vs baseline: 1.2607x; 1.0817x over previous
#include <cuda_runtime.h>
#include <stdint.h>

// GridGCNNearNeighbors, R10: fused float4{x,y,z,|p|^2} plane, no prefetch,
// occupancy-forced launch bounds (TLP over ILP).
//
// For each (b, s) centroid, emit the 32 smallest point indices with squared
// distance <= 0.2^2 (reference: mask -> sort ascending indices -> take 32 ==
// first-32 in-radius indices in index order), padding with the first hit.
//
// Inputs identified by element count (harness delivers int64 as int32):
//   pos        float32 [8, 8192, 3]  -> 196608 elements (unique)
//   centroids  int32   [8, 2048]     -> 16384 elements (unique)
// Output: float32 [8, 2048, 32] (indices stored as floats, exact <= 8192)

namespace {
constexpr int Bb = 8;
constexpr int Nn = 8192;
constexpr int Ss = 2048;
constexpr int Kk = 32;
constexpr float THR = 0.04f;  // (float)(0.2**2)
}

// Fused SoA plane: one float4 {x, y, z, |p|^2} per point (1 MB static scratch)
__device__ __align__(16) float4 g_p[Bb * Nn];

__global__ __launch_bounds__(256)
void soa_transpose_kernel(const float* __restrict__ pos) {
    const int i = blockIdx.x * blockDim.x + threadIdx.x;
    if (i >= Bb * Nn) return;
    const float* p = pos + (size_t)i * 3;
    const float x = p[0], y = p[1], z = p[2];
    g_p[i] = make_float4(x, y, z, x * x + y * y + z * z);
}

__global__ __launch_bounds__(64, 24)
void gridgcn_knn_kernel(const int* __restrict__ centroids,
                        float* __restrict__ out) {
    const int warp_id = (blockIdx.x << 1) | (threadIdx.x >> 5);
    const int lane = threadIdx.x & 31;
    if (warp_id >= Bb * Ss) return;

    const int b = warp_id >> 11;          // / 2048
    const int c = centroids[warp_id] & (Nn - 1);
    const float4* __restrict__ pp = g_p + b * Nn;

    // Center coordinates (warp-uniform broadcast; same bits as original pos)
    const float4 cp = pp[c];
    const float cx = cp.x, cy = cp.y, cz = cp.z;
    // Same expansion form as reference: ||c||^2 + ||p||^2 - 2 c.p
    const float sc = cx * cx + cy * cy + cz * cz;

    float* __restrict__ o = out + (size_t)warp_id * Kk;

    int have = 0;
    int first_idx = Nn;
    const unsigned below = (1u << lane) - 1u;
    const unsigned mybit = 1u << lane;

    #pragma unroll 1
    for (int base = 0; base < Nn; base += 128) {
        // Four independent coalesced LDG.128 (one per 32-point group)
        const float4 p0 = pp[base + lane];
        const float4 p1 = pp[base + 32 + lane];
        const float4 p2 = pp[base + 64 + lane];
        const float4 p3 = pp[base + 96 + lane];

        const float d20 = sc + p0.w - 2.0f * (cx * p0.x + cy * p0.y + cz * p0.z);
        const float d21 = sc + p1.w - 2.0f * (cx * p1.x + cy * p1.y + cz * p1.z);
        const float d22 = sc + p2.w - 2.0f * (cx * p2.x + cy * p2.y + cz * p2.z);
        const float d23 = sc + p3.w - 2.0f * (cx * p3.x + cy * p3.y + cz * p3.z);

        // m_k bit l  <->  point  base + 32*k + l  (simple group-major order)
        const unsigned m0 = __ballot_sync(0xffffffffu, d20 <= THR);
        const unsigned m1 = __ballot_sync(0xffffffffu, d21 <= THR);
        const unsigned m2 = __ballot_sync(0xffffffffu, d22 <= THR);
        const unsigned m3 = __ballot_sync(0xffffffffu, d23 <= THR);

        if (m0 | m1 | m2 | m3) {
            if (have == 0) {
                if (m0)      first_idx = base + __ffs(m0) - 1;
                else if (m1) first_idx = base + 32 + __ffs(m1) - 1;
                else if (m2) first_idx = base + 64 + __ffs(m2) - 1;
                else         first_idx = base + 96 + __ffs(m3) - 1;
            }
            int cum = have;
            {
                const int s = cum + __popc(m0 & below);
                if ((m0 & mybit) && s < Kk) o[s] = (float)(base + lane);
                cum += __popc(m0);
            }
            {
                const int s = cum + __popc(m1 & below);
                if ((m1 & mybit) && s < Kk) o[s] = (float)(base + 32 + lane);
                cum += __popc(m1);
            }
            {
                const int s = cum + __popc(m2 & below);
                if ((m2 & mybit) && s < Kk) o[s] = (float)(base + 64 + lane);
                cum += __popc(m2);
            }
            {
                const int s = cum + __popc(m3 & below);
                if ((m3 & mybit) && s < Kk) o[s] = (float)(base + 96 + lane);
                cum += __popc(m3);
            }
            have = cum;
            if (have >= Kk) break;
        }
    }

    // Pad tail with group_first (warp-uniform value)
    const float fpad = (float)first_idx;
    for (int i = have + lane; i < Kk; i += 32) o[i] = fpad;
}

extern "C" void kernel_launch(void* const* d_in, const int* in_sizes, int n_in,
                              void* d_out, int out_size) {
    (void)out_size;
    const float* pos = nullptr;
    const int* centroids = nullptr;
    for (int i = 0; i < n_in; i++) {
        if (in_sizes[i] == Bb * Nn * 3)      pos = (const float*)d_in[i];
        else if (in_sizes[i] == Bb * Ss)     centroids = (const int*)d_in[i];
    }
    float* out = (float*)d_out;

    soa_transpose_kernel<<<(Bb * Nn + 255) / 256, 256>>>(pos);

    const int total_warps = Bb * Ss;           // 16384
    const int threads = 64;                    // 2 warps/block
    const int blocks = total_warps / 2;        // 8192
    gridgcn_knn_kernel<<<blocks, threads>>>(centroids, out);
}